// round 4
// baseline (speedup 1.0000x reference)
#include <cuda_runtime.h>
#include <mma.h>
#include <math.h>

using namespace nvcuda;

// Problem constants
#define BATCH 64
#define HW    56
#define SEQ   3136
#define EMB   96
#define HEADS 3
#define EH    32
#define WS    7
#define WS2   49
#define NWIN  64

#define SCALE 0.17677669529663687f  // 1/sqrt(32)

// Scratch (device globals — no runtime allocation allowed)
__device__ float g_Q[BATCH * HEADS * NWIN * WS2 * EH];
__device__ float g_K[BATCH * HEADS * NWIN * WS2 * EH];
__device__ float g_V[BATCH * HEADS * NWIN * WS2 * EH];
__device__ float g_O[BATCH * SEQ * EMB];

// ---------------------------------------------------------------------------
// K1: qkv = x @ w1^T + b1 (tf32 wmma), fused roll(-4,-4) + window scatter.
// Block tile 64(M) x 96(N), K=96 chunked 2x48. 256 threads = 8 warps (4x2).
// ---------------------------------------------------------------------------
__global__ __launch_bounds__(256) void k_qkv(const float* __restrict__ x,
                                             const float* __restrict__ w1,
                                             const float* __restrict__ b1) {
    __shared__ float smem[8128];
    float (*xs)[52]  = (float(*)[52])smem;               // 64 x 52 (ld 52)
    float (*ws)[100] = (float(*)[100])(smem + 64 * 52);  // 48 x 100
    float (*Cs)[100] = (float(*)[100])smem;              // 64 x 100 (reuse)

    const int row0 = blockIdx.x * 64;
    const int c0   = blockIdx.y * 96;
    const int t    = threadIdx.x;
    const int w    = t >> 5;
    const int m0   = (w >> 1) * 16;
    const int n0   = (w & 1) * 48;

    wmma::fragment<wmma::accumulator, 16, 16, 8, float> acc[3];
    #pragma unroll
    for (int f = 0; f < 3; f++) wmma::fill_fragment(acc[f], 0.f);

    for (int kc = 0; kc < 96; kc += 48) {
        for (int i = t; i < 64 * 48; i += 256) {
            int r = i / 48, k = i % 48;
            xs[r][k] = x[(row0 + r) * 96 + kc + k];
        }
        for (int i = t; i < 48 * 96; i += 256) {
            int k = i / 96, n = i % 96;
            ws[k][n] = w1[(c0 + n) * 96 + kc + k];
        }
        __syncthreads();

        #pragma unroll
        for (int ks = 0; ks < 48; ks += 8) {
            wmma::fragment<wmma::matrix_a, 16, 16, 8, wmma::precision::tf32, wmma::row_major> a;
            wmma::load_matrix_sync(a, &xs[m0][ks], 52);
            #pragma unroll
            for (int i = 0; i < a.num_elements; i++) a.x[i] = wmma::__float_to_tf32(a.x[i]);
            #pragma unroll
            for (int f = 0; f < 3; f++) {
                wmma::fragment<wmma::matrix_b, 16, 16, 8, wmma::precision::tf32, wmma::row_major> bf;
                wmma::load_matrix_sync(bf, &ws[ks][n0 + f * 16], 100);
                #pragma unroll
                for (int i = 0; i < bf.num_elements; i++) bf.x[i] = wmma::__float_to_tf32(bf.x[i]);
                wmma::mma_sync(acc[f], a, bf, acc[f]);
            }
        }
        __syncthreads();
    }

    #pragma unroll
    for (int f = 0; f < 3; f++)
        wmma::store_matrix_sync(&Cs[m0][n0 + f * 16], acc[f], 100, wmma::mem_row_major);
    __syncthreads();

    // Scatter: bias + roll(-4,-4) + window partition
    for (int i = t; i < 64 * 96; i += 256) {
        const int r = i / 96, j = i % 96;
        const int row = row0 + r;
        const int b   = row / SEQ;
        const int s   = row % SEQ;
        const int y   = s / HW;
        const int xx  = s % HW;
        const int yr = (y + HW - 4) % HW;
        const int xr = (xx + HW - 4) % HW;
        const int wh = yr / WS, m1 = yr % WS;
        const int ww = xr / WS, m2 = xr % WS;
        const int win = wh * 8 + ww;
        const int m = m1 * WS + m2;
        const int col = c0 + j;
        const float v = Cs[r][j] + __ldg(&b1[col]);
        const int k = col % 3;
        const int e = col / 3;
        const int head = e >> 5;
        const int eh = e & 31;
        const int dst = (((b * HEADS + head) * NWIN + win) * WS2 + m) * EH + eh;
        if (k == 0)      g_Q[dst] = v;
        else if (k == 1) g_K[dst] = v;
        else             g_V[dst] = v;
    }
}

// ---------------------------------------------------------------------------
// K2: window attention via tf32 wmma (49 padded to 64). One block per
// (b, head, window), 128 threads = 4 warps. Epilogue: inverse roll, dense O.
// ---------------------------------------------------------------------------
__global__ __launch_bounds__(128) void k_attn() {
    __shared__ float Qs[64][36];
    __shared__ float Ks[64][36];
    __shared__ float Vs[64][36];
    __shared__ float Ss[64][68];

    const int blk = blockIdx.x;
    const int win = blk & 63;
    const int head = (blk >> 6) % 3;
    const int b = blk / (NWIN * HEADS);
    const int base = ((b * HEADS + head) * NWIN + win) * WS2 * EH;
    const int t = threadIdx.x;
    const int w = t >> 5, lane = t & 31;
    const int m0 = w * 16;

    // Load Q/K/V, zero-pad rows 49..63
    for (int i = t; i < 64 * EH; i += 128) {
        const int m = i >> 5, k = i & 31;
        float q = 0.f, kk = 0.f, vv = 0.f;
        if (m < WS2) {
            const int g = base + m * EH + k;
            q = g_Q[g]; kk = g_K[g]; vv = g_V[g];
        }
        Qs[m][k] = q; Ks[m][k] = kk; Vs[m][k] = vv;
    }
    __syncthreads();

    // S = Q @ K^T  (warp w computes rows m0..m0+15, all 64 cols)
    {
        wmma::fragment<wmma::accumulator, 16, 16, 8, float> sfr[4];
        #pragma unroll
        for (int f = 0; f < 4; f++) wmma::fill_fragment(sfr[f], 0.f);
        #pragma unroll
        for (int ks = 0; ks < EH; ks += 8) {
            wmma::fragment<wmma::matrix_a, 16, 16, 8, wmma::precision::tf32, wmma::row_major> a;
            wmma::load_matrix_sync(a, &Qs[m0][ks], 36);
            #pragma unroll
            for (int i = 0; i < a.num_elements; i++) a.x[i] = wmma::__float_to_tf32(a.x[i]);
            #pragma unroll
            for (int f = 0; f < 4; f++) {
                wmma::fragment<wmma::matrix_b, 16, 16, 8, wmma::precision::tf32, wmma::col_major> bf;
                wmma::load_matrix_sync(bf, &Ks[f * 16][ks], 36);
                #pragma unroll
                for (int i = 0; i < bf.num_elements; i++) bf.x[i] = wmma::__float_to_tf32(bf.x[i]);
                wmma::mma_sync(sfr[f], a, bf, sfr[f]);
            }
        }
        #pragma unroll
        for (int f = 0; f < 4; f++)
            wmma::store_matrix_sync(&Ss[m0][f * 16], sfr[f], 68, wmma::mem_row_major);
    }
    __syncthreads();

    // Masked softmax over valid cols [0,49); zero cols 49..63
    const int wh = win >> 3, ww = win & 7;
    const bool lastRow = (wh == 7);
    const bool lastCol = (ww == 7);
    for (int m = w; m < WS2; m += 4) {
        const int c1 = lane + 32;
        float s0 = Ss[m][lane] * SCALE;
        float s1 = (lane < 17) ? Ss[m][c1] * SCALE : -1e30f;
        const bool mr = (m / 7 >= 4), mc = (m % 7 >= 4);
        if ((lastRow && (mr != (lane / 7 >= 4))) ||
            (lastCol && (mc != (lane % 7 >= 4)))) s0 = -1e30f;
        if (lane < 17) {
            if ((lastRow && (mr != (c1 / 7 >= 4))) ||
                (lastCol && (mc != (c1 % 7 >= 4)))) s1 = -1e30f;
        }
        float mx = fmaxf(s0, s1);
        #pragma unroll
        for (int off = 16; off > 0; off >>= 1)
            mx = fmaxf(mx, __shfl_xor_sync(0xffffffff, mx, off));
        float e0 = __expf(s0 - mx);
        float e1 = (lane < 17) ? __expf(s1 - mx) : 0.f;
        float sm = e0 + e1;
        #pragma unroll
        for (int off = 16; off > 0; off >>= 1)
            sm += __shfl_xor_sync(0xffffffff, sm, off);
        const float inv = __frcp_rn(sm);
        Ss[m][lane] = e0 * inv;
        Ss[m][c1] = (lane < 17) ? e1 * inv : 0.f;
    }
    __syncthreads();

    // O = P @ V  (warp w: rows m0..m0+15, 32 cols); stage into Qs
    {
        wmma::fragment<wmma::accumulator, 16, 16, 8, float> ofr[2];
        #pragma unroll
        for (int f = 0; f < 2; f++) wmma::fill_fragment(ofr[f], 0.f);
        #pragma unroll
        for (int ks = 0; ks < 64; ks += 8) {
            wmma::fragment<wmma::matrix_a, 16, 16, 8, wmma::precision::tf32, wmma::row_major> a;
            wmma::load_matrix_sync(a, &Ss[m0][ks], 68);
            #pragma unroll
            for (int i = 0; i < a.num_elements; i++) a.x[i] = wmma::__float_to_tf32(a.x[i]);
            #pragma unroll
            for (int f = 0; f < 2; f++) {
                wmma::fragment<wmma::matrix_b, 16, 16, 8, wmma::precision::tf32, wmma::row_major> bf;
                wmma::load_matrix_sync(bf, &Vs[ks][f * 16], 36);
                #pragma unroll
                for (int i = 0; i < bf.num_elements; i++) bf.x[i] = wmma::__float_to_tf32(bf.x[i]);
                wmma::mma_sync(ofr[f], a, bf, ofr[f]);
            }
        }
        #pragma unroll
        for (int f = 0; f < 2; f++)
            wmma::store_matrix_sync(&Qs[m0][f * 16], ofr[f], 36, wmma::mem_row_major);
    }
    __syncthreads();

    // Scatter with inverse roll(+3,+3)
    for (int idx = t; idx < WS2 * EH; idx += 128) {
        const int m = idx >> 5, eh = idx & 31;
        const int m1 = m / 7, m2 = m % 7;
        const int y  = (wh * WS + m1 + 3) % HW;
        const int xx = (ww * WS + m2 + 3) % HW;
        g_O[(b * SEQ + y * HW + xx) * EMB + head * EH + eh] = Qs[m][eh];
    }
}

// ---------------------------------------------------------------------------
// K3: out = O @ w2^T + b2 (tf32 wmma). Tile 64x96, K=96 chunked 2x48.
// ---------------------------------------------------------------------------
__global__ __launch_bounds__(256) void k_proj(const float* __restrict__ w2,
                                              const float* __restrict__ b2,
                                              float* __restrict__ out) {
    __shared__ float smem[8128];
    float (*os)[52]  = (float(*)[52])smem;
    float (*ws)[100] = (float(*)[100])(smem + 64 * 52);
    float (*Cs)[100] = (float(*)[100])smem;

    const int row0 = blockIdx.x * 64;
    const int t = threadIdx.x;
    const int w = t >> 5;
    const int m0 = (w >> 1) * 16;
    const int n0 = (w & 1) * 48;

    wmma::fragment<wmma::accumulator, 16, 16, 8, float> acc[3];
    #pragma unroll
    for (int f = 0; f < 3; f++) wmma::fill_fragment(acc[f], 0.f);

    for (int kc = 0; kc < 96; kc += 48) {
        for (int i = t; i < 64 * 48; i += 256) {
            int r = i / 48, k = i % 48;
            os[r][k] = g_O[(row0 + r) * 96 + kc + k];
        }
        for (int i = t; i < 48 * 96; i += 256) {
            int k = i / 96, n = i % 96;
            ws[k][n] = w2[n * 96 + kc + k];
        }
        __syncthreads();

        #pragma unroll
        for (int ks = 0; ks < 48; ks += 8) {
            wmma::fragment<wmma::matrix_a, 16, 16, 8, wmma::precision::tf32, wmma::row_major> a;
            wmma::load_matrix_sync(a, &os[m0][ks], 52);
            #pragma unroll
            for (int i = 0; i < a.num_elements; i++) a.x[i] = wmma::__float_to_tf32(a.x[i]);
            #pragma unroll
            for (int f = 0; f < 3; f++) {
                wmma::fragment<wmma::matrix_b, 16, 16, 8, wmma::precision::tf32, wmma::row_major> bf;
                wmma::load_matrix_sync(bf, &ws[ks][n0 + f * 16], 100);
                #pragma unroll
                for (int i = 0; i < bf.num_elements; i++) bf.x[i] = wmma::__float_to_tf32(bf.x[i]);
                wmma::mma_sync(acc[f], a, bf, acc[f]);
            }
        }
        __syncthreads();
    }

    #pragma unroll
    for (int f = 0; f < 3; f++)
        wmma::store_matrix_sync(&Cs[m0][n0 + f * 16], acc[f], 100, wmma::mem_row_major);
    __syncthreads();

    for (int i = t; i < 64 * 96; i += 256) {
        const int r = i / 96, j = i % 96;
        out[(row0 + r) * 96 + j] = Cs[r][j] + __ldg(&b2[j]);
    }
}

// ---------------------------------------------------------------------------
extern "C" void kernel_launch(void* const* d_in, const int* in_sizes, int n_in,
                              void* d_out, int out_size) {
    const float* x  = (const float*)d_in[0];
    const float* w1 = (const float*)d_in[1];
    const float* b1 = (const float*)d_in[2];
    const float* w2 = (const float*)d_in[3];
    const float* b2 = (const float*)d_in[4];
    float* out = (float*)d_out;

    dim3 g1(SEQ * BATCH / 64, 3);
    k_qkv<<<g1, 256>>>(x, w1, b1);
    k_attn<<<BATCH * HEADS * NWIN, 128>>>();
    k_proj<<<SEQ * BATCH / 64, 256>>>(w2, b2, out);
}

// round 5
// speedup vs baseline: 1.6103x; 1.6103x over previous
#include <cuda_runtime.h>
#include <mma.h>
#include <math.h>

using namespace nvcuda;

#define BATCH 64
#define HW    56
#define SEQ   3136
#define EMB   96
#define HEADS 3
#define EH    32
#define WS    7
#define WS2   49
#define NWIN  64

#define SCALE 0.17677669529663687f  // 1/sqrt(32)

// Scratch (device globals)
__device__ float g_Q[BATCH * HEADS * NWIN * WS2 * EH];
__device__ float g_K[BATCH * HEADS * NWIN * WS2 * EH];
__device__ float g_V[BATCH * HEADS * NWIN * WS2 * EH];
__device__ float g_O[BATCH * SEQ * EMB];

__device__ __forceinline__ void mma_tf32(float& d0, float& d1, float& d2, float& d3,
                                         unsigned a0, unsigned a1, unsigned a2, unsigned a3,
                                         unsigned b0, unsigned b1) {
    asm volatile(
        "mma.sync.aligned.m16n8k8.row.col.f32.tf32.tf32.f32 "
        "{%0,%1,%2,%3}, {%4,%5,%6,%7}, {%8,%9}, {%0,%1,%2,%3};\n"
        : "+f"(d0), "+f"(d1), "+f"(d2), "+f"(d3)
        : "r"(a0), "r"(a1), "r"(a2), "r"(a3), "r"(b0), "r"(b1));
}

// ---------------------------------------------------------------------------
// K1: qkv = x @ w1^T + b1 via mma.sync tf32, swizzled staging (convert once).
// Block tile 128(M) x 96(N), K in 2 chunks of 48. 256 threads = 8 warps (4x2).
// Warp: 32 rows x 48 cols = 2 A-frags x 6 B-frags per k-step.
// Epilogue: fused roll(-4,-4) + window scatter into g_Q/g_K/g_V.
// ---------------------------------------------------------------------------
__global__ __launch_bounds__(256) void k_qkv(const float* __restrict__ x,
                                             const float* __restrict__ w1,
                                             const float* __restrict__ b1) {
    // A staged in fragment layout: As[((g*6+ks)*32 + lane)*4 + i_idx]
    // B staged:                    Bs[((ks*12+nblk)*32 + lane)*2 + i_idx]
    __shared__ float As[8 * 6 * 32 * 4];   // 6144 floats
    __shared__ float Bs[6 * 12 * 32 * 2];  // 4608 floats

    const int M0 = blockIdx.x * 128;
    const int c0 = blockIdx.y * 96;
    const int t = threadIdx.x;
    const int lane = t & 31;
    const int w = t >> 5;
    const int mw = w >> 1;     // 0..3
    const int nw = w & 1;      // 0..1
    const int gID = lane >> 2;
    const int tig = lane & 3;

    float d[2][6][4];
    #pragma unroll
    for (int f = 0; f < 2; f++)
        #pragma unroll
        for (int nb = 0; nb < 6; nb++)
            #pragma unroll
            for (int c = 0; c < 4; c++) d[f][nb][c] = 0.f;

    for (int kc = 0; kc < 96; kc += 48) {
        __syncthreads();
        // Stage A chunk [128 x 48], convert to tf32, swizzle to frag layout
        for (int i = t; i < 1536; i += 256) {
            const int r = i / 12, c4 = i % 12;
            const float4 v = *(const float4*)&x[(M0 + r) * 96 + kc + c4 * 4];
            const int g = r >> 4, rr = r & 15;
            const int ks = c4 >> 1, hi = c4 & 1;
            const int base = ((g * 6 + ks) * 32 + (rr & 7) * 4) * 4 + (rr >> 3) + 2 * hi;
            As[base + 0]  = wmma::__float_to_tf32(v.x);
            As[base + 4]  = wmma::__float_to_tf32(v.y);
            As[base + 8]  = wmma::__float_to_tf32(v.z);
            As[base + 12] = wmma::__float_to_tf32(v.w);
        }
        // Stage B chunk: B[k][n] = w1[c0+n][kc+k], [48 x 96]
        for (int i = t; i < 1152; i += 256) {
            const int n = i / 12, kq = i % 12;
            const float4 v = *(const float4*)&w1[(c0 + n) * 96 + kc + kq * 4];
            const int nblk = n >> 3, nn = n & 7;
            const int ks = kq >> 1, ii = kq & 1;
            const int base = ((ks * 12 + nblk) * 32 + nn * 4) * 2 + ii;
            Bs[base + 0] = wmma::__float_to_tf32(v.x);
            Bs[base + 2] = wmma::__float_to_tf32(v.y);
            Bs[base + 4] = wmma::__float_to_tf32(v.z);
            Bs[base + 6] = wmma::__float_to_tf32(v.w);
        }
        __syncthreads();

        const float4* A4 = (const float4*)As;
        const float2* B2 = (const float2*)Bs;
        #pragma unroll
        for (int ks = 0; ks < 6; ks++) {
            const float4 a0 = A4[((mw * 2 + 0) * 6 + ks) * 32 + lane];
            const float4 a1 = A4[((mw * 2 + 1) * 6 + ks) * 32 + lane];
            float2 bf[6];
            #pragma unroll
            for (int nb = 0; nb < 6; nb++)
                bf[nb] = B2[(ks * 12 + nw * 6 + nb) * 32 + lane];
            #pragma unroll
            for (int nb = 0; nb < 6; nb++) {
                mma_tf32(d[0][nb][0], d[0][nb][1], d[0][nb][2], d[0][nb][3],
                         __float_as_uint(a0.x), __float_as_uint(a0.y),
                         __float_as_uint(a0.z), __float_as_uint(a0.w),
                         __float_as_uint(bf[nb].x), __float_as_uint(bf[nb].y));
                mma_tf32(d[1][nb][0], d[1][nb][1], d[1][nb][2], d[1][nb][3],
                         __float_as_uint(a1.x), __float_as_uint(a1.y),
                         __float_as_uint(a1.z), __float_as_uint(a1.w),
                         __float_as_uint(bf[nb].x), __float_as_uint(bf[nb].y));
            }
        }
    }

    // Epilogue: bias + roll(-4,-4) + window scatter, straight from registers
    #pragma unroll
    for (int f = 0; f < 2; f++) {
        #pragma unroll
        for (int h = 0; h < 2; h++) {
            const int row = M0 + mw * 32 + f * 16 + gID + 8 * h;
            const int b   = row / SEQ;
            const int s   = row % SEQ;
            const int y   = s / HW;
            const int xx  = s % HW;
            const int yr  = (y + HW - 4) % HW;
            const int xr  = (xx + HW - 4) % HW;
            const int wh  = yr / WS, m1 = yr % WS;
            const int ww  = xr / WS, m2 = xr % WS;
            const int win = wh * 8 + ww;
            const int m   = m1 * WS + m2;
            const int t0  = b * 3 * 100352 + win * 1568 + m * 32;
            #pragma unroll
            for (int nb = 0; nb < 6; nb++) {
                #pragma unroll
                for (int cb = 0; cb < 2; cb++) {
                    const int col = c0 + nw * 48 + nb * 8 + tig * 2 + cb;
                    const float v = d[f][nb][h * 2 + cb] + __ldg(&b1[col]);
                    const int ksel = col % 3;
                    const int e    = col / 3;
                    const int head = e >> 5;
                    const int eh   = e & 31;
                    const int dst  = t0 + head * 100352 + eh;
                    if (ksel == 0)      g_Q[dst] = v;
                    else if (ksel == 1) g_K[dst] = v;
                    else                g_V[dst] = v;
                }
            }
        }
    }
}

// ---------------------------------------------------------------------------
// K2: window attention (tf32 wmma, conversions hoisted to staging, smem
// overlay S onto Q/K region). One block per (b, head, window), 128 threads.
// ---------------------------------------------------------------------------
__global__ __launch_bounds__(128) void k_attn() {
    __shared__ float sm[6912];
    float (*Qs)[36] = (float(*)[36])sm;           // 64x36 = 2304
    float (*Ks)[36] = (float(*)[36])(sm + 2304);  // 64x36
    float (*Vs)[36] = (float(*)[36])(sm + 4608);  // 64x36
    float (*Ss)[68] = (float(*)[68])sm;           // 64x68 = 4352 (overlays Qs/Ks)
    float (*Os)[36] = (float(*)[36])sm;           // 64x36 (overlays Ss after P.V)

    const int blk = blockIdx.x;
    const int win = blk & 63;
    const int head = (blk >> 6) % 3;
    const int b = blk / (NWIN * HEADS);
    const int base = ((b * HEADS + head) * NWIN + win) * WS2 * EH;
    const int t = threadIdx.x;
    const int w = t >> 5, lane = t & 31;
    const int m0 = w * 16;

    // Stage Q(*scale)/K/V, convert to tf32 once, zero-pad rows 49..63
    for (int i = t; i < 64 * EH; i += 128) {
        const int m = i >> 5, k = i & 31;
        float q = 0.f, kk = 0.f, vv = 0.f;
        if (m < WS2) {
            const int g = base + m * EH + k;
            q = g_Q[g] * SCALE; kk = g_K[g]; vv = g_V[g];
        }
        Qs[m][k] = wmma::__float_to_tf32(q);
        Ks[m][k] = wmma::__float_to_tf32(kk);
        Vs[m][k] = wmma::__float_to_tf32(vv);
    }
    __syncthreads();

    // S = Q @ K^T  (warp w: rows m0..m0+15, all 64 cols) — no conversions
    wmma::fragment<wmma::accumulator, 16, 16, 8, float> sfr[4];
    #pragma unroll
    for (int f = 0; f < 4; f++) wmma::fill_fragment(sfr[f], 0.f);
    #pragma unroll
    for (int ks = 0; ks < EH; ks += 8) {
        wmma::fragment<wmma::matrix_a, 16, 16, 8, wmma::precision::tf32, wmma::row_major> a;
        wmma::load_matrix_sync(a, &Qs[m0][ks], 36);
        #pragma unroll
        for (int f = 0; f < 4; f++) {
            wmma::fragment<wmma::matrix_b, 16, 16, 8, wmma::precision::tf32, wmma::col_major> bf;
            wmma::load_matrix_sync(bf, &Ks[f * 16][ks], 36);
            wmma::mma_sync(sfr[f], a, bf, sfr[f]);
        }
    }
    __syncthreads();   // all warps done reading Qs/Ks before S overlays them
    #pragma unroll
    for (int f = 0; f < 4; f++)
        wmma::store_matrix_sync(&Ss[m0][f * 16], sfr[f], 68, wmma::mem_row_major);
    __syncthreads();

    // Masked softmax over valid cols [0,49); P written back as tf32
    const int wh = win >> 3, ww = win & 7;
    const bool lastRow = (wh == 7);
    const bool lastCol = (ww == 7);
    for (int m = w; m < WS2; m += 4) {
        const int c1 = lane + 32;
        float s0 = Ss[m][lane];
        float s1 = (lane < 17) ? Ss[m][c1] : -1e30f;
        const bool mr = (m / 7 >= 4), mc = (m % 7 >= 4);
        if ((lastRow && (mr != (lane / 7 >= 4))) ||
            (lastCol && (mc != (lane % 7 >= 4)))) s0 = -1e30f;
        if (lane < 17) {
            if ((lastRow && (mr != (c1 / 7 >= 4))) ||
                (lastCol && (mc != (c1 % 7 >= 4)))) s1 = -1e30f;
        }
        float mx = fmaxf(s0, s1);
        #pragma unroll
        for (int off = 16; off > 0; off >>= 1)
            mx = fmaxf(mx, __shfl_xor_sync(0xffffffff, mx, off));
        float e0 = __expf(s0 - mx);
        float e1 = (lane < 17) ? __expf(s1 - mx) : 0.f;
        float smv = e0 + e1;
        #pragma unroll
        for (int off = 16; off > 0; off >>= 1)
            smv += __shfl_xor_sync(0xffffffff, smv, off);
        const float inv = __frcp_rn(smv);
        Ss[m][lane] = wmma::__float_to_tf32(e0 * inv);
        if (lane < 17) Ss[m][c1] = wmma::__float_to_tf32(e1 * inv);
    }
    __syncthreads();

    // O = P @ V  (warp w: rows m0..m0+15, 32 cols)
    wmma::fragment<wmma::accumulator, 16, 16, 8, float> ofr[2];
    #pragma unroll
    for (int f = 0; f < 2; f++) wmma::fill_fragment(ofr[f], 0.f);
    #pragma unroll
    for (int ks = 0; ks < 64; ks += 8) {
        wmma::fragment<wmma::matrix_a, 16, 16, 8, wmma::precision::tf32, wmma::row_major> a;
        wmma::load_matrix_sync(a, &Ss[m0][ks], 68);
        #pragma unroll
        for (int f = 0; f < 2; f++) {
            wmma::fragment<wmma::matrix_b, 16, 16, 8, wmma::precision::tf32, wmma::row_major> bf;
            wmma::load_matrix_sync(bf, &Vs[ks][f * 16], 36);
            wmma::mma_sync(ofr[f], a, bf, ofr[f]);
        }
    }
    __syncthreads();   // all warps done reading Ss before O overlays it
    #pragma unroll
    for (int f = 0; f < 2; f++)
        wmma::store_matrix_sync(&Os[m0][f * 16], ofr[f], 36, wmma::mem_row_major);
    __syncthreads();

    // Scatter with inverse roll(+3,+3)
    for (int idx = t; idx < WS2 * EH; idx += 128) {
        const int m = idx >> 5, eh = idx & 31;
        const int m1 = m / 7, m2 = m % 7;
        const int y  = (wh * WS + m1 + 3) % HW;
        const int xx = (ww * WS + m2 + 3) % HW;
        g_O[(b * SEQ + y * HW + xx) * EMB + head * EH + eh] = Os[m][eh];
    }
}

// ---------------------------------------------------------------------------
// K3: out = O @ w2^T + b2 via mma.sync tf32, same structure as K1, dense write.
// ---------------------------------------------------------------------------
__global__ __launch_bounds__(256) void k_proj(const float* __restrict__ w2,
                                              const float* __restrict__ b2,
                                              float* __restrict__ out) {
    __shared__ float As[8 * 6 * 32 * 4];
    __shared__ float Bs[6 * 12 * 32 * 2];

    const int M0 = blockIdx.x * 128;
    const int t = threadIdx.x;
    const int lane = t & 31;
    const int w = t >> 5;
    const int mw = w >> 1;
    const int nw = w & 1;
    const int gID = lane >> 2;
    const int tig = lane & 3;

    float d[2][6][4];
    #pragma unroll
    for (int f = 0; f < 2; f++)
        #pragma unroll
        for (int nb = 0; nb < 6; nb++)
            #pragma unroll
            for (int c = 0; c < 4; c++) d[f][nb][c] = 0.f;

    for (int kc = 0; kc < 96; kc += 48) {
        __syncthreads();
        for (int i = t; i < 1536; i += 256) {
            const int r = i / 12, c4 = i % 12;
            const float4 v = *(const float4*)&g_O[(M0 + r) * 96 + kc + c4 * 4];
            const int g = r >> 4, rr = r & 15;
            const int ks = c4 >> 1, hi = c4 & 1;
            const int base = ((g * 6 + ks) * 32 + (rr & 7) * 4) * 4 + (rr >> 3) + 2 * hi;
            As[base + 0]  = wmma::__float_to_tf32(v.x);
            As[base + 4]  = wmma::__float_to_tf32(v.y);
            As[base + 8]  = wmma::__float_to_tf32(v.z);
            As[base + 12] = wmma::__float_to_tf32(v.w);
        }
        for (int i = t; i < 1152; i += 256) {
            const int n = i / 12, kq = i % 12;
            const float4 v = *(const float4*)&w2[n * 96 + kc + kq * 4];
            const int nblk = n >> 3, nn = n & 7;
            const int ks = kq >> 1, ii = kq & 1;
            const int base = ((ks * 12 + nblk) * 32 + nn * 4) * 2 + ii;
            Bs[base + 0] = wmma::__float_to_tf32(v.x);
            Bs[base + 2] = wmma::__float_to_tf32(v.y);
            Bs[base + 4] = wmma::__float_to_tf32(v.z);
            Bs[base + 6] = wmma::__float_to_tf32(v.w);
        }
        __syncthreads();

        const float4* A4 = (const float4*)As;
        const float2* B2 = (const float2*)Bs;
        #pragma unroll
        for (int ks = 0; ks < 6; ks++) {
            const float4 a0 = A4[((mw * 2 + 0) * 6 + ks) * 32 + lane];
            const float4 a1 = A4[((mw * 2 + 1) * 6 + ks) * 32 + lane];
            float2 bf[6];
            #pragma unroll
            for (int nb = 0; nb < 6; nb++)
                bf[nb] = B2[(ks * 12 + nw * 6 + nb) * 32 + lane];
            #pragma unroll
            for (int nb = 0; nb < 6; nb++) {
                mma_tf32(d[0][nb][0], d[0][nb][1], d[0][nb][2], d[0][nb][3],
                         __float_as_uint(a0.x), __float_as_uint(a0.y),
                         __float_as_uint(a0.z), __float_as_uint(a0.w),
                         __float_as_uint(bf[nb].x), __float_as_uint(bf[nb].y));
                mma_tf32(d[1][nb][0], d[1][nb][1], d[1][nb][2], d[1][nb][3],
                         __float_as_uint(a1.x), __float_as_uint(a1.y),
                         __float_as_uint(a1.z), __float_as_uint(a1.w),
                         __float_as_uint(bf[nb].x), __float_as_uint(bf[nb].y));
            }
        }
    }

    #pragma unroll
    for (int f = 0; f < 2; f++) {
        #pragma unroll
        for (int h = 0; h < 2; h++) {
            const int row = M0 + mw * 32 + f * 16 + gID + 8 * h;
            #pragma unroll
            for (int nb = 0; nb < 6; nb++) {
                const int colp = nw * 48 + nb * 8 + tig * 2;
                float2 o;
                o.x = d[f][nb][h * 2 + 0] + __ldg(&b2[colp]);
                o.y = d[f][nb][h * 2 + 1] + __ldg(&b2[colp + 1]);
                *(float2*)&out[row * 96 + colp] = o;
            }
        }
    }
}

// ---------------------------------------------------------------------------
extern "C" void kernel_launch(void* const* d_in, const int* in_sizes, int n_in,
                              void* d_out, int out_size) {
    const float* x  = (const float*)d_in[0];
    const float* w1 = (const float*)d_in[1];
    const float* b1 = (const float*)d_in[2];
    const float* w2 = (const float*)d_in[3];
    const float* b2 = (const float*)d_in[4];
    float* out = (float*)d_out;

    dim3 g1(SEQ * BATCH / 128, 3);
    k_qkv<<<g1, 256>>>(x, w1, b1);
    k_attn<<<BATCH * HEADS * NWIN, 128>>>();
    k_proj<<<SEQ * BATCH / 128, 256>>>(w2, b2, out);
}

// round 6
// speedup vs baseline: 1.7177x; 1.0667x over previous
#include <cuda_runtime.h>
#include <mma.h>
#include <math.h>

using namespace nvcuda;

#define BATCH 64
#define HW    56
#define SEQ   3136
#define EMB   96
#define HEADS 3
#define EH    32
#define WS    7
#define WS2   49
#define NWIN  64

#define SCALE 0.17677669529663687f  // 1/sqrt(32)

// Scratch (device globals)
__device__ float g_Q[BATCH * HEADS * NWIN * WS2 * EH];
__device__ float g_K[BATCH * HEADS * NWIN * WS2 * EH];
__device__ float g_V[BATCH * HEADS * NWIN * WS2 * EH];
__device__ float g_O[BATCH * SEQ * EMB];

__device__ __forceinline__ void mma_tf32(float& d0, float& d1, float& d2, float& d3,
                                         unsigned a0, unsigned a1, unsigned a2, unsigned a3,
                                         unsigned b0, unsigned b1) {
    asm volatile(
        "mma.sync.aligned.m16n8k8.row.col.f32.tf32.tf32.f32 "
        "{%0,%1,%2,%3}, {%4,%5,%6,%7}, {%8,%9}, {%0,%1,%2,%3};\n"
        : "+f"(d0), "+f"(d1), "+f"(d2), "+f"(d3)
        : "r"(a0), "r"(a1), "r"(a2), "r"(a3), "r"(b0), "r"(b1));
}

// ---------------------------------------------------------------------------
// K1: qkv = x @ w1^T + b1 via mma.sync tf32.
// Block tile 128(M) x 96(N), K in 2 chunks of 48. 256 threads = 8 warps (4x2).
// Epilogue: stage C to SMEM (two 64-row halves), then fully coalesced 128B
// stores into g_Q/g_K/g_V (head = colTile, eh = lane, buffer = col%3).
// ---------------------------------------------------------------------------
__global__ __launch_bounds__(256) void k_qkv(const float* __restrict__ x,
                                             const float* __restrict__ w1,
                                             const float* __restrict__ b1) {
    __shared__ float smem[10752];          // union: As(6144) + Bs(4608) / Cs(6208)
    float* As = smem;                      // frag layout [ (g*6+ks)*32 + lane ]*4
    float* Bs = smem + 6144;               // frag layout [ (ks*12+nblk)*32 + lane ]*2
    float (*Cs)[97] = (float(*)[97])smem;  // 64 x 97 overlay (epilogue)

    const int M0 = blockIdx.x * 128;
    const int colTile = blockIdx.y;        // 0..2  (c0 = 96*colTile)
    const int c0 = colTile * 96;
    const int t = threadIdx.x;
    const int lane = t & 31;
    const int w = t >> 5;
    const int mw = w >> 1;     // 0..3
    const int nw = w & 1;      // 0..1
    const int gID = lane >> 2;
    const int tig = lane & 3;

    float d[2][6][4];
    #pragma unroll
    for (int f = 0; f < 2; f++)
        #pragma unroll
        for (int nb = 0; nb < 6; nb++)
            #pragma unroll
            for (int c = 0; c < 4; c++) d[f][nb][c] = 0.f;

    for (int kc = 0; kc < 96; kc += 48) {
        __syncthreads();
        // Stage A chunk [128 x 48] -> tf32 frag layout
        for (int i = t; i < 1536; i += 256) {
            const int r = i / 12, c4 = i % 12;
            const float4 v = *(const float4*)&x[(M0 + r) * 96 + kc + c4 * 4];
            const int g = r >> 4, rr = r & 15;
            const int ks = c4 >> 1, hi = c4 & 1;
            const int base = ((g * 6 + ks) * 32 + (rr & 7) * 4) * 4 + (rr >> 3) + 2 * hi;
            As[base + 0]  = wmma::__float_to_tf32(v.x);
            As[base + 4]  = wmma::__float_to_tf32(v.y);
            As[base + 8]  = wmma::__float_to_tf32(v.z);
            As[base + 12] = wmma::__float_to_tf32(v.w);
        }
        // Stage B chunk: B[k][n] = w1[c0+n][kc+k]
        for (int i = t; i < 1152; i += 256) {
            const int n = i / 12, kq = i % 12;
            const float4 v = *(const float4*)&w1[(c0 + n) * 96 + kc + kq * 4];
            const int nblk = n >> 3, nn = n & 7;
            const int ks = kq >> 1, ii = kq & 1;
            const int base = ((ks * 12 + nblk) * 32 + nn * 4) * 2 + ii;
            Bs[base + 0] = wmma::__float_to_tf32(v.x);
            Bs[base + 2] = wmma::__float_to_tf32(v.y);
            Bs[base + 4] = wmma::__float_to_tf32(v.z);
            Bs[base + 6] = wmma::__float_to_tf32(v.w);
        }
        __syncthreads();

        const float4* A4 = (const float4*)As;
        const float2* B2 = (const float2*)Bs;
        #pragma unroll
        for (int ks = 0; ks < 6; ks++) {
            const float4 a0 = A4[((mw * 2 + 0) * 6 + ks) * 32 + lane];
            const float4 a1 = A4[((mw * 2 + 1) * 6 + ks) * 32 + lane];
            float2 bf[6];
            #pragma unroll
            for (int nb = 0; nb < 6; nb++)
                bf[nb] = B2[(ks * 12 + nw * 6 + nb) * 32 + lane];
            #pragma unroll
            for (int nb = 0; nb < 6; nb++) {
                mma_tf32(d[0][nb][0], d[0][nb][1], d[0][nb][2], d[0][nb][3],
                         __float_as_uint(a0.x), __float_as_uint(a0.y),
                         __float_as_uint(a0.z), __float_as_uint(a0.w),
                         __float_as_uint(bf[nb].x), __float_as_uint(bf[nb].y));
                mma_tf32(d[1][nb][0], d[1][nb][1], d[1][nb][2], d[1][nb][3],
                         __float_as_uint(a1.x), __float_as_uint(a1.y),
                         __float_as_uint(a1.z), __float_as_uint(a1.w),
                         __float_as_uint(bf[nb].x), __float_as_uint(bf[nb].y));
            }
        }
    }

    // Epilogue in two 64-row halves (f = 0,1). Local row lr = mw*16 + gID + 8h,
    // global row = M0 + mw*32 + f*16 + (lr % 16).
    const float bias = __ldg(&b1[c0 + lane * 3 + 0]);   // sel handled below per-task
    (void)bias;
    #pragma unroll
    for (int f = 0; f < 2; f++) {
        __syncthreads();   // As/Bs (or previous half) fully consumed
        #pragma unroll
        for (int h = 0; h < 2; h++) {
            const int lr = mw * 16 + gID + 8 * h;
            #pragma unroll
            for (int nb = 0; nb < 6; nb++) {
                Cs[lr][nw * 48 + nb * 8 + tig * 2 + 0] = d[f][nb][h * 2 + 0];
                Cs[lr][nw * 48 + nb * 8 + tig * 2 + 1] = d[f][nb][h * 2 + 1];
            }
        }
        __syncthreads();
        // 192 warp-tasks: (row_l, sel). Each warp emits one 128B store.
        for (int p = w; p < 192; p += 8) {
            const int row_l = p / 3;        // 0..63 (local)
            const int sel   = p - row_l * 3;
            const int mwr = row_l >> 4;
            const int row = M0 + mwr * 32 + f * 16 + (row_l & 15);
            const int b   = row / SEQ;
            const int s   = row % SEQ;
            const int y   = s / HW;
            const int xx  = s % HW;
            const int yr  = (y + HW - 4) % HW;
            const int xr  = (xx + HW - 4) % HW;
            const int wh  = yr / WS, m1 = yr % WS;
            const int ww  = xr / WS, m2 = xr % WS;
            const int win = wh * 8 + ww;
            const int m   = m1 * WS + m2;
            const int dst = (((b * HEADS + colTile) * NWIN + win) * WS2 + m) * EH + lane;
            const float v = Cs[row_l][lane * 3 + sel] + __ldg(&b1[c0 + lane * 3 + sel]);
            if (sel == 0)      g_Q[dst] = v;
            else if (sel == 1) g_K[dst] = v;
            else               g_V[dst] = v;
        }
    }
}

// ---------------------------------------------------------------------------
// K2: window attention (tf32 wmma, conversions hoisted to staging, smem
// overlay S onto Q/K region). One block per (b, head, window), 128 threads.
// ---------------------------------------------------------------------------
__global__ __launch_bounds__(128) void k_attn() {
    __shared__ float sm[6912];
    float (*Qs)[36] = (float(*)[36])sm;           // 64x36 = 2304
    float (*Ks)[36] = (float(*)[36])(sm + 2304);  // 64x36
    float (*Vs)[36] = (float(*)[36])(sm + 4608);  // 64x36
    float (*Ss)[68] = (float(*)[68])sm;           // 64x68 = 4352 (overlays Qs/Ks)
    float (*Os)[36] = (float(*)[36])sm;           // 64x36 (overlays Ss after P.V)

    const int blk = blockIdx.x;
    const int win = blk & 63;
    const int head = (blk >> 6) % 3;
    const int b = blk / (NWIN * HEADS);
    const int base = ((b * HEADS + head) * NWIN + win) * WS2 * EH;
    const int t = threadIdx.x;
    const int w = t >> 5, lane = t & 31;
    const int m0 = w * 16;

    // Stage Q(*scale)/K/V, convert to tf32 once, zero-pad rows 49..63
    for (int i = t; i < 64 * EH; i += 128) {
        const int m = i >> 5, k = i & 31;
        float q = 0.f, kk = 0.f, vv = 0.f;
        if (m < WS2) {
            const int g = base + m * EH + k;
            q = g_Q[g] * SCALE; kk = g_K[g]; vv = g_V[g];
        }
        Qs[m][k] = wmma::__float_to_tf32(q);
        Ks[m][k] = wmma::__float_to_tf32(kk);
        Vs[m][k] = wmma::__float_to_tf32(vv);
    }
    __syncthreads();

    // S = Q @ K^T  (warp w: rows m0..m0+15, all 64 cols)
    wmma::fragment<wmma::accumulator, 16, 16, 8, float> sfr[4];
    #pragma unroll
    for (int f = 0; f < 4; f++) wmma::fill_fragment(sfr[f], 0.f);
    #pragma unroll
    for (int ks = 0; ks < EH; ks += 8) {
        wmma::fragment<wmma::matrix_a, 16, 16, 8, wmma::precision::tf32, wmma::row_major> a;
        wmma::load_matrix_sync(a, &Qs[m0][ks], 36);
        #pragma unroll
        for (int f = 0; f < 4; f++) {
            wmma::fragment<wmma::matrix_b, 16, 16, 8, wmma::precision::tf32, wmma::col_major> bf;
            wmma::load_matrix_sync(bf, &Ks[f * 16][ks], 36);
            wmma::mma_sync(sfr[f], a, bf, sfr[f]);
        }
    }
    __syncthreads();   // all warps done reading Qs/Ks before S overlays them
    #pragma unroll
    for (int f = 0; f < 4; f++)
        wmma::store_matrix_sync(&Ss[m0][f * 16], sfr[f], 68, wmma::mem_row_major);
    __syncthreads();

    // Masked softmax over valid cols [0,49); P written back as tf32
    const int wh = win >> 3, ww = win & 7;
    const bool lastRow = (wh == 7);
    const bool lastCol = (ww == 7);
    for (int m = w; m < WS2; m += 4) {
        const int c1 = lane + 32;
        float s0 = Ss[m][lane];
        float s1 = (lane < 17) ? Ss[m][c1] : -1e30f;
        const bool mr = (m / 7 >= 4), mc = (m % 7 >= 4);
        if ((lastRow && (mr != (lane / 7 >= 4))) ||
            (lastCol && (mc != (lane % 7 >= 4)))) s0 = -1e30f;
        if (lane < 17) {
            if ((lastRow && (mr != (c1 / 7 >= 4))) ||
                (lastCol && (mc != (c1 % 7 >= 4)))) s1 = -1e30f;
        }
        float mx = fmaxf(s0, s1);
        #pragma unroll
        for (int off = 16; off > 0; off >>= 1)
            mx = fmaxf(mx, __shfl_xor_sync(0xffffffff, mx, off));
        float e0 = __expf(s0 - mx);
        float e1 = (lane < 17) ? __expf(s1 - mx) : 0.f;
        float smv = e0 + e1;
        #pragma unroll
        for (int off = 16; off > 0; off >>= 1)
            smv += __shfl_xor_sync(0xffffffff, smv, off);
        const float inv = __frcp_rn(smv);
        Ss[m][lane] = wmma::__float_to_tf32(e0 * inv);
        if (lane < 17) Ss[m][c1] = wmma::__float_to_tf32(e1 * inv);
    }
    __syncthreads();

    // O = P @ V  (warp w: rows m0..m0+15, 32 cols)
    wmma::fragment<wmma::accumulator, 16, 16, 8, float> ofr[2];
    #pragma unroll
    for (int f = 0; f < 2; f++) wmma::fill_fragment(ofr[f], 0.f);
    #pragma unroll
    for (int ks = 0; ks < 64; ks += 8) {
        wmma::fragment<wmma::matrix_a, 16, 16, 8, wmma::precision::tf32, wmma::row_major> a;
        wmma::load_matrix_sync(a, &Ss[m0][ks], 68);
        #pragma unroll
        for (int f = 0; f < 2; f++) {
            wmma::fragment<wmma::matrix_b, 16, 16, 8, wmma::precision::tf32, wmma::row_major> bf;
            wmma::load_matrix_sync(bf, &Vs[ks][f * 16], 36);
            wmma::mma_sync(ofr[f], a, bf, ofr[f]);
        }
    }
    __syncthreads();   // all warps done reading Ss before O overlays it
    #pragma unroll
    for (int f = 0; f < 2; f++)
        wmma::store_matrix_sync(&Os[m0][f * 16], ofr[f], 36, wmma::mem_row_major);
    __syncthreads();

    // Scatter with inverse roll(+3,+3)
    for (int idx = t; idx < WS2 * EH; idx += 128) {
        const int m = idx >> 5, eh = idx & 31;
        const int m1 = m / 7, m2 = m % 7;
        const int y  = (wh * WS + m1 + 3) % HW;
        const int xx = (ww * WS + m2 + 3) % HW;
        g_O[(b * SEQ + y * HW + xx) * EMB + head * EH + eh] = Os[m][eh];
    }
}

// ---------------------------------------------------------------------------
// K3: out = O @ w2^T + b2 via mma.sync tf32, dense coalesced write.
// ---------------------------------------------------------------------------
__global__ __launch_bounds__(256) void k_proj(const float* __restrict__ w2,
                                              const float* __restrict__ b2,
                                              float* __restrict__ out) {
    __shared__ float As[8 * 6 * 32 * 4];
    __shared__ float Bs[6 * 12 * 32 * 2];

    const int M0 = blockIdx.x * 128;
    const int t = threadIdx.x;
    const int lane = t & 31;
    const int w = t >> 5;
    const int mw = w >> 1;
    const int nw = w & 1;
    const int gID = lane >> 2;
    const int tig = lane & 3;

    float d[2][6][4];
    #pragma unroll
    for (int f = 0; f < 2; f++)
        #pragma unroll
        for (int nb = 0; nb < 6; nb++)
            #pragma unroll
            for (int c = 0; c < 4; c++) d[f][nb][c] = 0.f;

    for (int kc = 0; kc < 96; kc += 48) {
        __syncthreads();
        for (int i = t; i < 1536; i += 256) {
            const int r = i / 12, c4 = i % 12;
            const float4 v = *(const float4*)&g_O[(M0 + r) * 96 + kc + c4 * 4];
            const int g = r >> 4, rr = r & 15;
            const int ks = c4 >> 1, hi = c4 & 1;
            const int base = ((g * 6 + ks) * 32 + (rr & 7) * 4) * 4 + (rr >> 3) + 2 * hi;
            As[base + 0]  = wmma::__float_to_tf32(v.x);
            As[base + 4]  = wmma::__float_to_tf32(v.y);
            As[base + 8]  = wmma::__float_to_tf32(v.z);
            As[base + 12] = wmma::__float_to_tf32(v.w);
        }
        for (int i = t; i < 1152; i += 256) {
            const int n = i / 12, kq = i % 12;
            const float4 v = *(const float4*)&w2[n * 96 + kc + kq * 4];
            const int nblk = n >> 3, nn = n & 7;
            const int ks = kq >> 1, ii = kq & 1;
            const int base = ((ks * 12 + nblk) * 32 + nn * 4) * 2 + ii;
            Bs[base + 0] = wmma::__float_to_tf32(v.x);
            Bs[base + 2] = wmma::__float_to_tf32(v.y);
            Bs[base + 4] = wmma::__float_to_tf32(v.z);
            Bs[base + 6] = wmma::__float_to_tf32(v.w);
        }
        __syncthreads();

        const float4* A4 = (const float4*)As;
        const float2* B2 = (const float2*)Bs;
        #pragma unroll
        for (int ks = 0; ks < 6; ks++) {
            const float4 a0 = A4[((mw * 2 + 0) * 6 + ks) * 32 + lane];
            const float4 a1 = A4[((mw * 2 + 1) * 6 + ks) * 32 + lane];
            float2 bf[6];
            #pragma unroll
            for (int nb = 0; nb < 6; nb++)
                bf[nb] = B2[(ks * 12 + nw * 6 + nb) * 32 + lane];
            #pragma unroll
            for (int nb = 0; nb < 6; nb++) {
                mma_tf32(d[0][nb][0], d[0][nb][1], d[0][nb][2], d[0][nb][3],
                         __float_as_uint(a0.x), __float_as_uint(a0.y),
                         __float_as_uint(a0.z), __float_as_uint(a0.w),
                         __float_as_uint(bf[nb].x), __float_as_uint(bf[nb].y));
                mma_tf32(d[1][nb][0], d[1][nb][1], d[1][nb][2], d[1][nb][3],
                         __float_as_uint(a1.x), __float_as_uint(a1.y),
                         __float_as_uint(a1.z), __float_as_uint(a1.w),
                         __float_as_uint(bf[nb].x), __float_as_uint(bf[nb].y));
            }
        }
    }

    #pragma unroll
    for (int f = 0; f < 2; f++) {
        #pragma unroll
        for (int h = 0; h < 2; h++) {
            const int row = M0 + mw * 32 + f * 16 + gID + 8 * h;
            #pragma unroll
            for (int nb = 0; nb < 6; nb++) {
                const int colp = nw * 48 + nb * 8 + tig * 2;
                float2 o;
                o.x = d[f][nb][h * 2 + 0] + __ldg(&b2[colp]);
                o.y = d[f][nb][h * 2 + 1] + __ldg(&b2[colp + 1]);
                *(float2*)&out[row * 96 + colp] = o;
            }
        }
    }
}

// ---------------------------------------------------------------------------
extern "C" void kernel_launch(void* const* d_in, const int* in_sizes, int n_in,
                              void* d_out, int out_size) {
    const float* x  = (const float*)d_in[0];
    const float* w1 = (const float*)d_in[1];
    const float* b1 = (const float*)d_in[2];
    const float* w2 = (const float*)d_in[3];
    const float* b2 = (const float*)d_in[4];
    float* out = (float*)d_out;

    dim3 g1(SEQ * BATCH / 128, 3);
    k_qkv<<<g1, 256>>>(x, w1, b1);
    k_attn<<<BATCH * HEADS * NWIN, 128>>>();
    k_proj<<<SEQ * BATCH / 128, 256>>>(w2, b2, out);
}

// round 7
// speedup vs baseline: 2.0359x; 1.1853x over previous
#include <cuda_runtime.h>
#include <mma.h>
#include <math.h>

using namespace nvcuda;

#define BATCH 64
#define HW    56
#define SEQ   3136
#define EMB   96
#define HEADS 3
#define EH    32
#define WS    7
#define WS2   49
#define NWIN  64

#define SCALE 0.17677669529663687f  // 1/sqrt(32)

// Scratch (device globals)
__device__ float g_Q[BATCH * HEADS * NWIN * WS2 * EH];
__device__ float g_K[BATCH * HEADS * NWIN * WS2 * EH];
__device__ float g_V[BATCH * HEADS * NWIN * WS2 * EH];
__device__ float g_O[BATCH * SEQ * EMB];

__device__ __forceinline__ void mma_tf32(float& d0, float& d1, float& d2, float& d3,
                                         unsigned a0, unsigned a1, unsigned a2, unsigned a3,
                                         unsigned b0, unsigned b1) {
    asm volatile(
        "mma.sync.aligned.m16n8k8.row.col.f32.tf32.tf32.f32 "
        "{%0,%1,%2,%3}, {%4,%5,%6,%7}, {%8,%9}, {%0,%1,%2,%3};\n"
        : "+f"(d0), "+f"(d1), "+f"(d2), "+f"(d3)
        : "r"(a0), "r"(a1), "r"(a2), "r"(a3), "r"(b0), "r"(b1));
}

// ---------------------------------------------------------------------------
// K1: qkv = x @ w1^T + b1 via mma.sync tf32.
// Block tile 128(M) x 96(N), K in 2 chunks of 48. 256 threads = 8 warps (4x2).
// Scatter addresses precomputed once per row (dstBase); coalesced 128B stores.
// ---------------------------------------------------------------------------
__global__ __launch_bounds__(256) void k_qkv(const float* __restrict__ x,
                                             const float* __restrict__ w1,
                                             const float* __restrict__ b1) {
    __shared__ float smem[10752];          // union: As(6144)+Bs(4608) / Cs(64x97)
    __shared__ int dstBase[128];
    float* As = smem;
    float* Bs = smem + 6144;
    float (*Cs)[97] = (float(*)[97])smem;

    const int M0 = blockIdx.x * 128;
    const int colTile = blockIdx.y;        // head index; c0 = 96*colTile
    const int c0 = colTile * 96;
    const int t = threadIdx.x;
    const int lane = t & 31;
    const int w = t >> 5;
    const int mw = w >> 1;     // 0..3
    const int nw = w & 1;      // 0..1
    const int gID = lane >> 2;
    const int tig = lane & 3;

    // Precompute per-row scatter base (once) and per-lane bias (3 values)
    if (t < 128) {
        const int row = M0 + t;
        const int b   = row / SEQ;
        const int s   = row % SEQ;
        const int y   = s / HW;
        const int xx  = s % HW;
        const int yr  = (y + HW - 4) % HW;
        const int xr  = (xx + HW - 4) % HW;
        const int wh  = yr / WS, m1 = yr % WS;
        const int ww  = xr / WS, m2 = xr % WS;
        const int win = wh * 8 + ww;
        const int m   = m1 * WS + m2;
        dstBase[t] = (((b * HEADS + colTile) * NWIN + win) * WS2 + m) * EH;
    }
    float bias[3];
    #pragma unroll
    for (int sel = 0; sel < 3; sel++) bias[sel] = __ldg(&b1[c0 + lane * 3 + sel]);

    // Per-thread staging coordinates (strength-reduced address math)
    const int rA = t >> 1, halfA = t & 1;          // A: 128 rows x 2 halves
    const int gA = rA >> 4, rrA = rA & 15;
    const int fbaseA = gA * 768 + (rrA & 7) * 16 + (rrA >> 3);
    const int ks0A = halfA * 3;
    const int nB = t >> 1, halfB = t & 1;          // B: 96 rows x 2 halves (t<192)
    const int fbaseB = (nB >> 3) * 64 + (nB & 7) * 8;
    const int ks0B = halfB * 3;

    float d[2][6][4];
    #pragma unroll
    for (int f = 0; f < 2; f++)
        #pragma unroll
        for (int nb = 0; nb < 6; nb++)
            #pragma unroll
            for (int c = 0; c < 4; c++) d[f][nb][c] = 0.f;

    for (int kc = 0; kc < 96; kc += 48) {
        __syncthreads();
        // Stage A chunk [128 x 48] -> tf32 frag layout
        {
            const float* xrow = &x[(M0 + rA) * 96 + kc + halfA * 24];
            #pragma unroll
            for (int j = 0; j < 6; j++) {
                const float4 v = *(const float4*)&xrow[j * 4];
                const int base = fbaseA + (ks0A + (j >> 1)) * 128 + 2 * (j & 1);
                As[base + 0]  = wmma::__float_to_tf32(v.x);
                As[base + 4]  = wmma::__float_to_tf32(v.y);
                As[base + 8]  = wmma::__float_to_tf32(v.z);
                As[base + 12] = wmma::__float_to_tf32(v.w);
            }
        }
        // Stage B chunk: B[k][n] = w1[c0+n][kc+k]
        if (t < 192) {
            const float* wrow = &w1[(c0 + nB) * 96 + kc + halfB * 24];
            #pragma unroll
            for (int j = 0; j < 6; j++) {
                const float4 v = *(const float4*)&wrow[j * 4];
                const int base = fbaseB + (ks0B + (j >> 1)) * 768 + (j & 1);
                Bs[base + 0] = wmma::__float_to_tf32(v.x);
                Bs[base + 2] = wmma::__float_to_tf32(v.y);
                Bs[base + 4] = wmma::__float_to_tf32(v.z);
                Bs[base + 6] = wmma::__float_to_tf32(v.w);
            }
        }
        __syncthreads();

        const float4* A4 = (const float4*)As;
        const float2* B2 = (const float2*)Bs;
        #pragma unroll
        for (int ks = 0; ks < 6; ks++) {
            const float4 a0 = A4[((mw * 2 + 0) * 6 + ks) * 32 + lane];
            const float4 a1 = A4[((mw * 2 + 1) * 6 + ks) * 32 + lane];
            float2 bf[6];
            #pragma unroll
            for (int nb = 0; nb < 6; nb++)
                bf[nb] = B2[(ks * 12 + nw * 6 + nb) * 32 + lane];
            #pragma unroll
            for (int nb = 0; nb < 6; nb++) {
                mma_tf32(d[0][nb][0], d[0][nb][1], d[0][nb][2], d[0][nb][3],
                         __float_as_uint(a0.x), __float_as_uint(a0.y),
                         __float_as_uint(a0.z), __float_as_uint(a0.w),
                         __float_as_uint(bf[nb].x), __float_as_uint(bf[nb].y));
                mma_tf32(d[1][nb][0], d[1][nb][1], d[1][nb][2], d[1][nb][3],
                         __float_as_uint(a1.x), __float_as_uint(a1.y),
                         __float_as_uint(a1.z), __float_as_uint(a1.w),
                         __float_as_uint(bf[nb].x), __float_as_uint(bf[nb].y));
            }
        }
    }

    // Epilogue in two 64-row halves
    #pragma unroll
    for (int f = 0; f < 2; f++) {
        __syncthreads();
        #pragma unroll
        for (int h = 0; h < 2; h++) {
            const int lr = mw * 16 + gID + 8 * h;
            #pragma unroll
            for (int nb = 0; nb < 6; nb++) {
                Cs[lr][nw * 48 + nb * 8 + tig * 2 + 0] = d[f][nb][h * 2 + 0];
                Cs[lr][nw * 48 + nb * 8 + tig * 2 + 1] = d[f][nb][h * 2 + 1];
            }
        }
        __syncthreads();
        // Each warp: 8 rows x 3 buffers, one 128B store each
        #pragma unroll
        for (int sel = 0; sel < 3; sel++) {
            #pragma unroll
            for (int r = 0; r < 64; r += 8) {
                const int row_l = r + w;
                const int gq = (row_l >> 4) * 32 + f * 16 + (row_l & 15);
                const int dst = dstBase[gq] + lane;
                const float v = Cs[row_l][lane * 3 + sel] + bias[sel];
                if (sel == 0)      g_Q[dst] = v;
                else if (sel == 1) g_K[dst] = v;
                else               g_V[dst] = v;
            }
        }
    }
}

// ---------------------------------------------------------------------------
// K2: window attention (tf32 wmma, conversions hoisted, smem overlays).
// One block per (b, head, window), 128 threads. (unchanged)
// ---------------------------------------------------------------------------
__global__ __launch_bounds__(128) void k_attn() {
    __shared__ float sm[6912];
    float (*Qs)[36] = (float(*)[36])sm;
    float (*Ks)[36] = (float(*)[36])(sm + 2304);
    float (*Vs)[36] = (float(*)[36])(sm + 4608);
    float (*Ss)[68] = (float(*)[68])sm;
    float (*Os)[36] = (float(*)[36])sm;

    const int blk = blockIdx.x;
    const int win = blk & 63;
    const int head = (blk >> 6) % 3;
    const int b = blk / (NWIN * HEADS);
    const int base = ((b * HEADS + head) * NWIN + win) * WS2 * EH;
    const int t = threadIdx.x;
    const int w = t >> 5, lane = t & 31;
    const int m0 = w * 16;

    for (int i = t; i < 64 * EH; i += 128) {
        const int m = i >> 5, k = i & 31;
        float q = 0.f, kk = 0.f, vv = 0.f;
        if (m < WS2) {
            const int g = base + m * EH + k;
            q = g_Q[g] * SCALE; kk = g_K[g]; vv = g_V[g];
        }
        Qs[m][k] = wmma::__float_to_tf32(q);
        Ks[m][k] = wmma::__float_to_tf32(kk);
        Vs[m][k] = wmma::__float_to_tf32(vv);
    }
    __syncthreads();

    wmma::fragment<wmma::accumulator, 16, 16, 8, float> sfr[4];
    #pragma unroll
    for (int f = 0; f < 4; f++) wmma::fill_fragment(sfr[f], 0.f);
    #pragma unroll
    for (int ks = 0; ks < EH; ks += 8) {
        wmma::fragment<wmma::matrix_a, 16, 16, 8, wmma::precision::tf32, wmma::row_major> a;
        wmma::load_matrix_sync(a, &Qs[m0][ks], 36);
        #pragma unroll
        for (int f = 0; f < 4; f++) {
            wmma::fragment<wmma::matrix_b, 16, 16, 8, wmma::precision::tf32, wmma::col_major> bf;
            wmma::load_matrix_sync(bf, &Ks[f * 16][ks], 36);
            wmma::mma_sync(sfr[f], a, bf, sfr[f]);
        }
    }
    __syncthreads();
    #pragma unroll
    for (int f = 0; f < 4; f++)
        wmma::store_matrix_sync(&Ss[m0][f * 16], sfr[f], 68, wmma::mem_row_major);
    __syncthreads();

    const int wh = win >> 3, ww = win & 7;
    const bool lastRow = (wh == 7);
    const bool lastCol = (ww == 7);
    for (int m = w; m < WS2; m += 4) {
        const int c1 = lane + 32;
        float s0 = Ss[m][lane];
        float s1 = (lane < 17) ? Ss[m][c1] : -1e30f;
        const bool mr = (m / 7 >= 4), mc = (m % 7 >= 4);
        if ((lastRow && (mr != (lane / 7 >= 4))) ||
            (lastCol && (mc != (lane % 7 >= 4)))) s0 = -1e30f;
        if (lane < 17) {
            if ((lastRow && (mr != (c1 / 7 >= 4))) ||
                (lastCol && (mc != (c1 % 7 >= 4)))) s1 = -1e30f;
        }
        float mx = fmaxf(s0, s1);
        #pragma unroll
        for (int off = 16; off > 0; off >>= 1)
            mx = fmaxf(mx, __shfl_xor_sync(0xffffffff, mx, off));
        float e0 = __expf(s0 - mx);
        float e1 = (lane < 17) ? __expf(s1 - mx) : 0.f;
        float smv = e0 + e1;
        #pragma unroll
        for (int off = 16; off > 0; off >>= 1)
            smv += __shfl_xor_sync(0xffffffff, smv, off);
        const float inv = __frcp_rn(smv);
        Ss[m][lane] = wmma::__float_to_tf32(e0 * inv);
        if (lane < 17) Ss[m][c1] = wmma::__float_to_tf32(e1 * inv);
    }
    __syncthreads();

    wmma::fragment<wmma::accumulator, 16, 16, 8, float> ofr[2];
    #pragma unroll
    for (int f = 0; f < 2; f++) wmma::fill_fragment(ofr[f], 0.f);
    #pragma unroll
    for (int ks = 0; ks < 64; ks += 8) {
        wmma::fragment<wmma::matrix_a, 16, 16, 8, wmma::precision::tf32, wmma::row_major> a;
        wmma::load_matrix_sync(a, &Ss[m0][ks], 68);
        #pragma unroll
        for (int f = 0; f < 2; f++) {
            wmma::fragment<wmma::matrix_b, 16, 16, 8, wmma::precision::tf32, wmma::row_major> bf;
            wmma::load_matrix_sync(bf, &Vs[ks][f * 16], 36);
            wmma::mma_sync(ofr[f], a, bf, ofr[f]);
        }
    }
    __syncthreads();
    #pragma unroll
    for (int f = 0; f < 2; f++)
        wmma::store_matrix_sync(&Os[m0][f * 16], ofr[f], 36, wmma::mem_row_major);
    __syncthreads();

    for (int idx = t; idx < WS2 * EH; idx += 128) {
        const int m = idx >> 5, eh = idx & 31;
        const int m1 = m / 7, m2 = m % 7;
        const int y  = (wh * WS + m1 + 3) % HW;
        const int xx = (ww * WS + m2 + 3) % HW;
        g_O[(b * SEQ + y * HW + xx) * EMB + head * EH + eh] = Os[m][eh];
    }
}

// ---------------------------------------------------------------------------
// K3: out = O @ w2^T + b2 via mma.sync tf32, dense coalesced write.
// ---------------------------------------------------------------------------
__global__ __launch_bounds__(256) void k_proj(const float* __restrict__ w2,
                                              const float* __restrict__ b2,
                                              float* __restrict__ out) {
    __shared__ float As[6144];
    __shared__ float Bs[4608];

    const int M0 = blockIdx.x * 128;
    const int t = threadIdx.x;
    const int lane = t & 31;
    const int w = t >> 5;
    const int mw = w >> 1;
    const int nw = w & 1;
    const int gID = lane >> 2;
    const int tig = lane & 3;

    const int rA = t >> 1, halfA = t & 1;
    const int gA = rA >> 4, rrA = rA & 15;
    const int fbaseA = gA * 768 + (rrA & 7) * 16 + (rrA >> 3);
    const int ks0A = halfA * 3;
    const int nB = t >> 1, halfB = t & 1;
    const int fbaseB = (nB >> 3) * 64 + (nB & 7) * 8;
    const int ks0B = halfB * 3;

    float d[2][6][4];
    #pragma unroll
    for (int f = 0; f < 2; f++)
        #pragma unroll
        for (int nb = 0; nb < 6; nb++)
            #pragma unroll
            for (int c = 0; c < 4; c++) d[f][nb][c] = 0.f;

    for (int kc = 0; kc < 96; kc += 48) {
        __syncthreads();
        {
            const float* orow = &g_O[(M0 + rA) * 96 + kc + halfA * 24];
            #pragma unroll
            for (int j = 0; j < 6; j++) {
                const float4 v = *(const float4*)&orow[j * 4];
                const int base = fbaseA + (ks0A + (j >> 1)) * 128 + 2 * (j & 1);
                As[base + 0]  = wmma::__float_to_tf32(v.x);
                As[base + 4]  = wmma::__float_to_tf32(v.y);
                As[base + 8]  = wmma::__float_to_tf32(v.z);
                As[base + 12] = wmma::__float_to_tf32(v.w);
            }
        }
        if (t < 192) {
            const float* wrow = &w2[nB * 96 + kc + halfB * 24];
            #pragma unroll
            for (int j = 0; j < 6; j++) {
                const float4 v = *(const float4*)&wrow[j * 4];
                const int base = fbaseB + (ks0B + (j >> 1)) * 768 + (j & 1);
                Bs[base + 0] = wmma::__float_to_tf32(v.x);
                Bs[base + 2] = wmma::__float_to_tf32(v.y);
                Bs[base + 4] = wmma::__float_to_tf32(v.z);
                Bs[base + 6] = wmma::__float_to_tf32(v.w);
            }
        }
        __syncthreads();

        const float4* A4 = (const float4*)As;
        const float2* B2 = (const float2*)Bs;
        #pragma unroll
        for (int ks = 0; ks < 6; ks++) {
            const float4 a0 = A4[((mw * 2 + 0) * 6 + ks) * 32 + lane];
            const float4 a1 = A4[((mw * 2 + 1) * 6 + ks) * 32 + lane];
            float2 bf[6];
            #pragma unroll
            for (int nb = 0; nb < 6; nb++)
                bf[nb] = B2[(ks * 12 + nw * 6 + nb) * 32 + lane];
            #pragma unroll
            for (int nb = 0; nb < 6; nb++) {
                mma_tf32(d[0][nb][0], d[0][nb][1], d[0][nb][2], d[0][nb][3],
                         __float_as_uint(a0.x), __float_as_uint(a0.y),
                         __float_as_uint(a0.z), __float_as_uint(a0.w),
                         __float_as_uint(bf[nb].x), __float_as_uint(bf[nb].y));
                mma_tf32(d[1][nb][0], d[1][nb][1], d[1][nb][2], d[1][nb][3],
                         __float_as_uint(a1.x), __float_as_uint(a1.y),
                         __float_as_uint(a1.z), __float_as_uint(a1.w),
                         __float_as_uint(bf[nb].x), __float_as_uint(bf[nb].y));
            }
        }
    }

    #pragma unroll
    for (int f = 0; f < 2; f++) {
        #pragma unroll
        for (int h = 0; h < 2; h++) {
            const int row = M0 + mw * 32 + f * 16 + gID + 8 * h;
            #pragma unroll
            for (int nb = 0; nb < 6; nb++) {
                const int colp = nw * 48 + nb * 8 + tig * 2;
                float2 o;
                o.x = d[f][nb][h * 2 + 0] + __ldg(&b2[colp]);
                o.y = d[f][nb][h * 2 + 1] + __ldg(&b2[colp + 1]);
                *(float2*)&out[row * 96 + colp] = o;
            }
        }
    }
}

// ---------------------------------------------------------------------------
extern "C" void kernel_launch(void* const* d_in, const int* in_sizes, int n_in,
                              void* d_out, int out_size) {
    const float* x  = (const float*)d_in[0];
    const float* w1 = (const float*)d_in[1];
    const float* b1 = (const float*)d_in[2];
    const float* w2 = (const float*)d_in[3];
    const float* b2 = (const float*)d_in[4];
    float* out = (float*)d_out;

    dim3 g1(SEQ * BATCH / 128, 3);
    k_qkv<<<g1, 256>>>(x, w1, b1);
    k_attn<<<BATCH * HEADS * NWIN, 128>>>();
    k_proj<<<SEQ * BATCH / 128, 256>>>(w2, b2, out);
}